// round 7
// baseline (speedup 1.0000x reference)
#include <cuda_runtime.h>
#include <cuda_bf16.h>
#include <cstdint>

// Problem constants
#define BB 8
#define NN 2048
#define KNN 16
#define NPTS (BB * NN)            // 16384
#define NEDGE (NPTS * KNN)        // 262144

// Static scratch (allocation-free rule)
__device__ float g_X0[NPTS * 256];
__device__ float g_X1[NPTS * 256];
__device__ float g_sqn[NPTS];
__device__ float g_S[(long long)BB * NN * NN];     // 134 MB distance scores
__device__ int   g_idx[NEDGE];
__device__ float g_PQ[NPTS * 1024];                // 64 MB  [P | Q] per node
__device__ float g_Wcat[256 * 1024];               // [Wd | W1b]
__device__ float g_bcat[1024];

// ---------------------------------------------------------------------------
// Generic 64x64 register-tiled SGEMM (fp32).
// epi: 0 = (+bias if bias!=null), 2 = dist: C = -2*acc + sqn[n]
// transB: 0 -> B[k*ldb+n], 1 -> B[n*ldb+k]
// ---------------------------------------------------------------------------
__global__ __launch_bounds__(256)
void sgemm64(const float* __restrict__ A, const float* __restrict__ B,
             const float* __restrict__ bias, const float* __restrict__ sqn,
             float* __restrict__ C,
             int M, int Nn, int Kd,
             int lda, int ldb, int ldc,
             int transB, int epi,
             long long sA, long long sB, long long sC, int sSqn)
{
    int bz = blockIdx.z;
    A += bz * sA;
    B += bz * sB;
    C += bz * sC;
    const float* sq = sqn ? (sqn + (long long)bz * sSqn) : nullptr;

    __shared__ float As[16][68];
    __shared__ float Bs[16][68];

    int t = threadIdx.x;
    int tx = t & 15, ty = t >> 4;
    int bm = blockIdx.y * 64, bn = blockIdx.x * 64;

    float acc[4][4];
#pragma unroll
    for (int i = 0; i < 4; i++)
#pragma unroll
        for (int j = 0; j < 4; j++) acc[i][j] = 0.f;

    for (int kt = 0; kt < Kd; kt += 16) {
#pragma unroll
        for (int e = t; e < 1024; e += 256) {
            int m = e >> 4, k = e & 15;
            int gm = bm + m, gk = kt + k;
            As[k][m] = (gm < M && gk < Kd) ? A[(long long)gm * lda + gk] : 0.f;
        }
        if (!transB) {
#pragma unroll
            for (int e = t; e < 1024; e += 256) {
                int k = e >> 6, n = e & 63;
                int gk = kt + k, gn = bn + n;
                Bs[k][n] = (gk < Kd && gn < Nn) ? B[(long long)gk * ldb + gn] : 0.f;
            }
        } else {
#pragma unroll
            for (int e = t; e < 1024; e += 256) {
                int n = e >> 4, k = e & 15;
                int gk = kt + k, gn = bn + n;
                Bs[k][n] = (gk < Kd && gn < Nn) ? B[(long long)gn * ldb + gk] : 0.f;
            }
        }
        __syncthreads();
#pragma unroll
        for (int k = 0; k < 16; k++) {
            float a[4], b[4];
#pragma unroll
            for (int i = 0; i < 4; i++) a[i] = As[k][ty * 4 + i];
#pragma unroll
            for (int j = 0; j < 4; j++) b[j] = Bs[k][tx * 4 + j];
#pragma unroll
            for (int i = 0; i < 4; i++)
#pragma unroll
                for (int j = 0; j < 4; j++) acc[i][j] += a[i] * b[j];
        }
        __syncthreads();
    }

#pragma unroll
    for (int i = 0; i < 4; i++) {
        int gm = bm + ty * 4 + i;
        if (gm >= M) continue;
#pragma unroll
        for (int j = 0; j < 4; j++) {
            int gn = bn + tx * 4 + j;
            if (gn >= Nn) continue;
            float v = acc[i][j];
            if (epi == 2) {
                v = -2.f * v + sq[gn];
            } else {
                if (bias) v += bias[gn];
            }
            C[(long long)gm * ldc + gn] = v;
        }
    }
}

// ---------------------------------------------------------------------------
// squared norms, one warp per row
// ---------------------------------------------------------------------------
__global__ void sqnorm_kernel(const float* __restrict__ X, float* __restrict__ sqn, int D)
{
    int warp = (blockIdx.x * blockDim.x + threadIdx.x) >> 5;
    int lane = threadIdx.x & 31;
    if (warp >= NPTS) return;
    const float* row = X + (long long)warp * D;
    float s = 0.f;
    for (int c = lane; c < D; c += 32) { float v = row[c]; s += v * v; }
#pragma unroll
    for (int off = 16; off; off >>= 1) s += __shfl_xor_sync(0xffffffffu, s, off);
    if (lane == 0) sqn[warp] = s;
}

// ---------------------------------------------------------------------------
// top-16 smallest per row (warp per row, 4 rows/block, iterative selection)
// ---------------------------------------------------------------------------
__global__ __launch_bounds__(128)
void topk_kernel(const float* __restrict__ S, int* __restrict__ idx)
{
    __shared__ float sm[4][NN];
    int warp = threadIdx.x >> 5, lane = threadIdx.x & 31;
    int r = blockIdx.x * 4 + warp;
    const float* row = S + (long long)r * NN;
    for (int j = lane; j < NN; j += 32) sm[warp][j] = row[j];
    __syncwarp();

    unsigned long long used = 0ull;
    for (int it = 0; it < KNN; it++) {
        float best = 3.4e38f;
        int bidx = 1 << 30;
#pragma unroll 8
        for (int tt = 0; tt < 64; tt++) {
            if (!((used >> tt) & 1ull)) {
                int j = lane + (tt << 5);
                float v = sm[warp][j];
                if (v < best || (v == best && j < bidx)) { best = v; bidx = j; }
            }
        }
#pragma unroll
        for (int off = 16; off; off >>= 1) {
            float ov = __shfl_xor_sync(0xffffffffu, best, off);
            int oi = __shfl_xor_sync(0xffffffffu, bidx, off);
            if (ov < best || (ov == best && oi < bidx)) { best = ov; bidx = oi; }
        }
        if ((bidx & 31) == lane) used |= 1ull << (bidx >> 5);
        if (lane == 0) idx[r * KNN + it] = bidx;
    }
}

// ---------------------------------------------------------------------------
// Wcat = [W1a - W1b | W1b]  (din x 2c2);  bcat = [b1 | 0]
// ---------------------------------------------------------------------------
__global__ void prep_kernel(const float* __restrict__ W1, const float* __restrict__ b1,
                            float* __restrict__ Wcat, float* __restrict__ bcat,
                            int din, int c2)
{
    int i = blockIdx.x * blockDim.x + threadIdx.x;
    int ld = 2 * c2;
    int total = din * ld;
    if (i < total) {
        int r = i / ld, c = i % ld;
        float v;
        if (c < c2) v = W1[r * c2 + c] - W1[(din + r) * c2 + c];
        else        v = W1[(din + r) * c2 + (c - c2)];
        Wcat[i] = v;
    }
    if (i < ld) bcat[i] = (i < c2) ? b1[i] : 0.f;
}

// ---------------------------------------------------------------------------
// tf32 split helpers
// ---------------------------------------------------------------------------
__device__ __forceinline__ float tf32_rna(float v)
{
    unsigned u;
    asm("cvt.rna.tf32.f32 %0, %1;" : "=r"(u) : "f"(v));
    return __uint_as_float(u);
}

// ---------------------------------------------------------------------------
// Fused edge kernel (tf32x3 tensor cores -> fp32-level accuracy):
//   For each edge e=(i,j): a_e = relu(P_i + Q_j)  (generated in A-tile fill)
//   H2_e = relu(a_e @ W2 + b2)
//   Xout[node] = mean over the node's 16 edges of H2_e
// Operands split v = hi + lo (tf32 each); acc += Alo*Bhi + Ahi*Blo + Ahi*Bhi.
// Block: 64 edges (= 4 complete nodes) x 64 output cols, 256 threads / 8 warps.
// ---------------------------------------------------------------------------
#define EKT 32
__global__ __launch_bounds__(256)
void edge_mma_kernel(const float* __restrict__ PQ, const int* __restrict__ idx,
                     const float* __restrict__ W2, const float* __restrict__ b2,
                     float* __restrict__ Xout, int c2, int dout)
{
    __shared__ float Ah[64][33], Al[64][33];
    __shared__ float Bh[EKT][65], Bl[EKT][65];
    __shared__ float Cs[64][65];
    __shared__ int   poff[64], qoff[64];
    __shared__ float bs2[64];

    int t = threadIdx.x;
    int bn = blockIdx.x * 64;
    int be = blockIdx.y * 64;
    int ld = 2 * c2;

    if (t < 64) {
        int e = be + t;
        int r = e >> 4;
        int b = r >> 11;
        int j = idx[e];
        poff[t] = r * ld;
        qoff[t] = ((b << 11) + j) * ld + c2;
        int gn = bn + t;
        bs2[t] = (gn < dout) ? b2[gn] : 0.f;
    }
    __syncthreads();

    int warp = t >> 5, lane = t & 31;
    int mrow = (warp >> 1) * 16;
    int ncol = (warp & 1) * 32;
    int gq = lane >> 2, tq = lane & 3;

    float acc[4][4];
#pragma unroll
    for (int f = 0; f < 4; f++)
#pragma unroll
        for (int i = 0; i < 4; i++) acc[f][i] = 0.f;

    for (int kt = 0; kt < c2; kt += EKT) {
        // A tile 64x32: relu(P_i + Q_j), split hi/lo
#pragma unroll
        for (int e = t; e < 64 * EKT; e += 256) {
            int m = e >> 5, k = e & 31;
            float v = fmaxf(PQ[poff[m] + kt + k] + PQ[qoff[m] + kt + k], 0.f);
            float hi = tf32_rna(v);
            Ah[m][k] = hi;
            Al[m][k] = tf32_rna(v - hi);
        }
        // B tile 32x64 from W2 [c2 x dout], split hi/lo
#pragma unroll
        for (int e = t; e < EKT * 64; e += 256) {
            int k = e >> 6, n = e & 63;
            int gn = bn + n;
            float v = (gn < dout) ? W2[(kt + k) * dout + gn] : 0.f;
            float hi = tf32_rna(v);
            Bh[k][n] = hi;
            Bl[k][n] = tf32_rna(v - hi);
        }
        __syncthreads();

#pragma unroll
        for (int k8 = 0; k8 < EKT; k8 += 8) {
            unsigned ah0 = __float_as_uint(Ah[mrow + gq][k8 + tq]);
            unsigned ah1 = __float_as_uint(Ah[mrow + gq + 8][k8 + tq]);
            unsigned ah2 = __float_as_uint(Ah[mrow + gq][k8 + tq + 4]);
            unsigned ah3 = __float_as_uint(Ah[mrow + gq + 8][k8 + tq + 4]);
            unsigned al0 = __float_as_uint(Al[mrow + gq][k8 + tq]);
            unsigned al1 = __float_as_uint(Al[mrow + gq + 8][k8 + tq]);
            unsigned al2 = __float_as_uint(Al[mrow + gq][k8 + tq + 4]);
            unsigned al3 = __float_as_uint(Al[mrow + gq + 8][k8 + tq + 4]);
#pragma unroll
            for (int f = 0; f < 4; f++) {
                unsigned bh0 = __float_as_uint(Bh[k8 + tq][ncol + f * 8 + gq]);
                unsigned bh1 = __float_as_uint(Bh[k8 + tq + 4][ncol + f * 8 + gq]);
                unsigned bl0 = __float_as_uint(Bl[k8 + tq][ncol + f * 8 + gq]);
                unsigned bl1 = __float_as_uint(Bl[k8 + tq + 4][ncol + f * 8 + gq]);
                // small terms first, then the dominant hi*hi
                asm volatile(
                    "mma.sync.aligned.m16n8k8.row.col.f32.tf32.tf32.f32 "
                    "{%0,%1,%2,%3}, {%4,%5,%6,%7}, {%8,%9}, {%0,%1,%2,%3};"
                    : "+f"(acc[f][0]), "+f"(acc[f][1]), "+f"(acc[f][2]), "+f"(acc[f][3])
                    : "r"(al0), "r"(al1), "r"(al2), "r"(al3), "r"(bh0), "r"(bh1));
                asm volatile(
                    "mma.sync.aligned.m16n8k8.row.col.f32.tf32.tf32.f32 "
                    "{%0,%1,%2,%3}, {%4,%5,%6,%7}, {%8,%9}, {%0,%1,%2,%3};"
                    : "+f"(acc[f][0]), "+f"(acc[f][1]), "+f"(acc[f][2]), "+f"(acc[f][3])
                    : "r"(ah0), "r"(ah1), "r"(ah2), "r"(ah3), "r"(bl0), "r"(bl1));
                asm volatile(
                    "mma.sync.aligned.m16n8k8.row.col.f32.tf32.tf32.f32 "
                    "{%0,%1,%2,%3}, {%4,%5,%6,%7}, {%8,%9}, {%0,%1,%2,%3};"
                    : "+f"(acc[f][0]), "+f"(acc[f][1]), "+f"(acc[f][2]), "+f"(acc[f][3])
                    : "r"(ah0), "r"(ah1), "r"(ah2), "r"(ah3), "r"(bh0), "r"(bh1));
            }
        }
        __syncthreads();
    }

    // epilogue: relu(acc + b2) per edge row into Cs
#pragma unroll
    for (int f = 0; f < 4; f++) {
        int c0 = ncol + f * 8 + tq * 2;
        Cs[mrow + gq][c0]         = fmaxf(acc[f][0] + bs2[c0], 0.f);
        Cs[mrow + gq][c0 + 1]     = fmaxf(acc[f][1] + bs2[c0 + 1], 0.f);
        Cs[mrow + gq + 8][c0]     = fmaxf(acc[f][2] + bs2[c0], 0.f);
        Cs[mrow + gq + 8][c0 + 1] = fmaxf(acc[f][3] + bs2[c0 + 1], 0.f);
    }
    __syncthreads();

    // mean over each node's 16 edge rows -> Xout
    int g = t >> 6, c = t & 63;
    int gn = bn + c;
    if (gn < dout) {
        float s = 0.f;
#pragma unroll
        for (int r = 0; r < 16; r++) s += Cs[g * 16 + r][c];
        int node = blockIdx.y * 4 + g;
        Xout[(long long)node * dout + gn] = s * (1.f / 16.f);
    }
}

// ---------------------------------------------------------------------------
// global mean pool + final linear -> [8,2]
// ---------------------------------------------------------------------------
__global__ void final_kernel(const float* __restrict__ X, const float* __restrict__ Wf,
                             const float* __restrict__ bf, float* __restrict__ out)
{
    __shared__ float pooled[BB][16];
    int t = threadIdx.x;
    if (t < 128) {
        int b = t >> 4, c = t & 15;
        float s = 0.f;
        const float* base = X + ((long long)b * NN) * 16 + c;
        for (int n = 0; n < NN; n++) s += base[n * 16];
        pooled[b][c] = s / (float)NN;
    }
    __syncthreads();
    if (t < 16) {
        int b = t >> 1, o = t & 1;
        float s = bf[o];
#pragma unroll
        for (int c = 0; c < 16; c++) s += pooled[b][c] * Wf[c * 2 + o];
        out[b * 2 + o] = s;
    }
}

// ---------------------------------------------------------------------------
extern "C" void kernel_launch(void* const* d_in, const int* in_sizes, int n_in,
                              void* d_out, int out_size)
{
    (void)in_sizes; (void)n_in; (void)out_size;
    static const int DIMS[7] = {3, 32, 128, 256, 64, 32, 16};

    float *X0, *X1, *S, *PQ, *Wcat, *bcat, *sqn;
    int* idxp;
    cudaGetSymbolAddress((void**)&X0,   g_X0);
    cudaGetSymbolAddress((void**)&X1,   g_X1);
    cudaGetSymbolAddress((void**)&S,    g_S);
    cudaGetSymbolAddress((void**)&PQ,   g_PQ);
    cudaGetSymbolAddress((void**)&Wcat, g_Wcat);
    cudaGetSymbolAddress((void**)&bcat, g_bcat);
    cudaGetSymbolAddress((void**)&sqn,  g_sqn);
    cudaGetSymbolAddress((void**)&idxp, g_idx);

    const float* cur = (const float*)d_in[0];

    for (int l = 0; l < 6; l++) {
        int din = DIMS[l], dout = DIMS[l + 1], c2 = 2 * dout;
        const float* W1 = (const float*)d_in[1 + 4 * l];
        const float* b1 = (const float*)d_in[2 + 4 * l];
        const float* W2 = (const float*)d_in[3 + 4 * l];
        const float* b2 = (const float*)d_in[4 + 4 * l];
        float* Xn = (l & 1) ? X1 : X0;

        // 1) squared norms
        sqnorm_kernel<<<NPTS * 32 / 256, 256>>>(cur, sqn, din);

        // 2) distance scores S = -2*X X^T + ||x_j||^2  (batched over B, fp32)
        sgemm64<<<dim3(NN / 64, NN / 64, BB), 256>>>(
            cur, cur, nullptr, sqn, S,
            NN, NN, din, din, din, NN,
            /*transB=*/1, /*epi=*/2,
            (long long)NN * din, (long long)NN * din, (long long)NN * NN, NN);

        // 3) top-16 neighbor indices
        topk_kernel<<<NPTS / 4, 128>>>(S, idxp);

        // 4) Wcat = [W1a-W1b | W1b], bcat = [b1 | 0]
        prep_kernel<<<(din * 2 * c2 + 255) / 256, 256>>>(W1, b1, Wcat, bcat, din, c2);

        // 5) PQ = X @ Wcat + bcat   -> [NPTS, 2c2] = [P | Q]
        sgemm64<<<dim3((2 * c2 + 63) / 64, NPTS / 64, 1), 256>>>(
            cur, Wcat, bcat, nullptr, PQ,
            NPTS, 2 * c2, din, din, 2 * c2, 2 * c2, 0, 0, 0, 0, 0, 0);

        // 6) fused: H1 gen + GEMM2 (tf32x3 tensor cores) + bias/relu + k-mean
        edge_mma_kernel<<<dim3((dout + 63) / 64, NEDGE / 64), 256>>>(
            PQ, idxp, W2, b2, Xn, c2, dout);

        cur = Xn;
    }

    final_kernel<<<1, 128>>>(cur, (const float*)d_in[25], (const float*)d_in[26],
                             (float*)d_out);
}